// round 10
// baseline (speedup 1.0000x reference)
#include <cuda_runtime.h>
#include <cuda_fp16.h>

#define N_NODES 100000
#define N_EDGES 1600000
#define D 64

#define SCAN_BLK 1024
#define SCAN_NBLK 98                 // 98*1024 = 100352 >= 100000
#define SCAN_PAD (SCAN_NBLK * SCAN_BLK)

#define BIN_BLOCKS  1563             // 1563*256*4 = 1600512 >= N_EDGES
#define GEMM_BLOCKS 1563             // 1563*64 = 100032 >= N_NODES

// Scratch (static __device__ arrays: allowed).
__device__ int   g_count[SCAN_PAD];
__device__ int   g_excl[SCAN_PAD];
__device__ int   g_bsum[SCAN_NBLK];
__device__ int   g_rowptr[N_NODES];
__device__ int   g_cursor[N_NODES];
__device__ int2  g_edges[N_EDGES];    // (src, w-as-int) binned by dst
__device__ uint2 g_Zh[N_NODES * 16];  // Z = X @ W in fp16: 64 halves/row = 128B

// ---------------------------------------------------------------------------
// 1) histogram of destination nodes — 4 edges/thread.
// ---------------------------------------------------------------------------
__global__ __launch_bounds__(256) void hist_kernel(const int* __restrict__ dst) {
    int e0 = (blockIdx.x * blockDim.x + threadIdx.x) * 4;
    if (e0 + 3 < N_EDGES) {
        int4 t = *reinterpret_cast<const int4*>(&dst[e0]);
        atomicAdd(&g_count[t.x], 1);
        atomicAdd(&g_count[t.y], 1);
        atomicAdd(&g_count[t.z], 1);
        atomicAdd(&g_count[t.w], 1);
    } else {
        for (int e = e0; e < N_EDGES; e++) atomicAdd(&g_count[__ldg(&dst[e])], 1);
    }
}

// ---------------------------------------------------------------------------
// 2a) per-block exclusive scan via warp shuffles (2 barriers).
// ---------------------------------------------------------------------------
__global__ __launch_bounds__(SCAN_BLK) void scan_a_kernel() {
    __shared__ int warp_sums[32];
    int t = threadIdx.x;
    int gid = blockIdx.x * SCAN_BLK + t;
    int lane = t & 31, wid = t >> 5;
    int c = g_count[gid];

    int v = c;                                 // inclusive scan within warp
    #pragma unroll
    for (int off = 1; off < 32; off <<= 1) {
        int n = __shfl_up_sync(0xFFFFFFFF, v, off);
        if (lane >= off) v += n;
    }
    if (lane == 31) warp_sums[wid] = v;
    __syncthreads();

    if (wid == 0) {
        int ws = warp_sums[lane];
        int s = ws;
        #pragma unroll
        for (int off = 1; off < 32; off <<= 1) {
            int n = __shfl_up_sync(0xFFFFFFFF, s, off);
            if (lane >= off) s += n;
        }
        warp_sums[lane] = s - ws;              // exclusive warp prefix
    }
    __syncthreads();

    g_excl[gid] = v - c + warp_sums[wid];      // block-exclusive
    if (t == SCAN_BLK - 1) g_bsum[blockIdx.x] = warp_sums[31] + v;
}

// 2b) finalize row_ptr (256 nodes per block lie inside one scan_a block).
__global__ __launch_bounds__(256) void scan_c_kernel() {
    __shared__ int s[SCAN_NBLK];
    __shared__ int prefix;
    int t = threadIdx.x;
    int sblk = blockIdx.x >> 2;
    if (t < SCAN_NBLK) s[t] = g_bsum[t];
    __syncthreads();
    if (t == 0) {
        int run = 0;
        for (int i = 0; i < sblk; i++) run += s[i];
        prefix = run;
    }
    __syncthreads();
    int i = blockIdx.x * 256 + t;
    if (i < N_NODES) {
        int v = g_excl[i] + prefix;
        g_rowptr[i] = v;
        g_cursor[i] = v;
    }
}

// ---------------------------------------------------------------------------
// 3) FUSED bin + gemm.  GEMM tiles now fp16 in smem (1B/FMA LDS, 16KB smem
//    -> higher occupancy for the latency-bound bin path). fp32 FMA math.
// ---------------------------------------------------------------------------
__global__ __launch_bounds__(256) void bin_gemm_kernel(
        const int*   __restrict__ src,
        const int*   __restrict__ dst,
        const float* __restrict__ w,
        const float* __restrict__ X,
        const float* __restrict__ W) {
    __shared__ __half smh[2 * D * D];        // Ws_h (8KB) + As_h (8KB)

    int part_id = blockIdx.x >> 1;

    if (blockIdx.x & 1) {
        // ---------------- GEMM tile path ----------------
        __half* Ws = smh;                    // [k][c]
        __half* As = smh + D * D;            // [r][k]
        int tid = threadIdx.x;
        int row0 = part_id * 64;

        // Fill Ws: 1024 float4 -> 1024 uint2 (4 halves each)
        const float4* W4 = reinterpret_cast<const float4*>(W);
        uint2* Ws2 = reinterpret_cast<uint2*>(Ws);
        #pragma unroll
        for (int i = tid; i < 1024; i += 256) {
            float4 v = W4[i];
            __half2 h01 = __floats2half2_rn(v.x, v.y);
            __half2 h23 = __floats2half2_rn(v.z, v.w);
            uint2 p;
            p.x = *reinterpret_cast<unsigned int*>(&h01);
            p.y = *reinterpret_cast<unsigned int*>(&h23);
            Ws2[i] = p;
        }

        const float4* A4 = reinterpret_cast<const float4*>(X) + row0 * 16;
        uint2* As2 = reinterpret_cast<uint2*>(As);
        #pragma unroll
        for (int i = tid; i < 1024; i += 256) {
            int r = i >> 4;
            float4 v = (row0 + r < N_NODES) ? A4[i]
                                            : make_float4(0.f, 0.f, 0.f, 0.f);
            __half2 h01 = __floats2half2_rn(v.x, v.y);
            __half2 h23 = __floats2half2_rn(v.z, v.w);
            uint2 p;
            p.x = *reinterpret_cast<unsigned int*>(&h01);
            p.y = *reinterpret_cast<unsigned int*>(&h23);
            As2[i] = p;
        }
        __syncthreads();

        int tx = tid & 15;
        int ty = tid >> 4;
        int c0 = tx * 4;
        int r0 = ty * 4;

        float4 acc[4];
        #pragma unroll
        for (int i = 0; i < 4; i++) acc[i] = make_float4(0.f, 0.f, 0.f, 0.f);

        #pragma unroll
        for (int k0 = 0; k0 < D; k0 += 4) {
            float4 wr[4];
            #pragma unroll
            for (int j = 0; j < 4; j++) {
                uint2 u = *reinterpret_cast<const uint2*>(&Ws[(k0 + j) * D + c0]);
                float2 f01 = __half22float2(*reinterpret_cast<__half2*>(&u.x));
                float2 f23 = __half22float2(*reinterpret_cast<__half2*>(&u.y));
                wr[j] = make_float4(f01.x, f01.y, f23.x, f23.y);
            }
            #pragma unroll
            for (int i = 0; i < 4; i++) {
                uint2 u = *reinterpret_cast<const uint2*>(&As[(r0 + i) * D + k0]);
                float2 a01 = __half22float2(*reinterpret_cast<__half2*>(&u.x));
                float2 a23 = __half22float2(*reinterpret_cast<__half2*>(&u.y));

                acc[i].x = fmaf(a01.x, wr[0].x, acc[i].x);
                acc[i].y = fmaf(a01.x, wr[0].y, acc[i].y);
                acc[i].z = fmaf(a01.x, wr[0].z, acc[i].z);
                acc[i].w = fmaf(a01.x, wr[0].w, acc[i].w);

                acc[i].x = fmaf(a01.y, wr[1].x, acc[i].x);
                acc[i].y = fmaf(a01.y, wr[1].y, acc[i].y);
                acc[i].z = fmaf(a01.y, wr[1].z, acc[i].z);
                acc[i].w = fmaf(a01.y, wr[1].w, acc[i].w);

                acc[i].x = fmaf(a23.x, wr[2].x, acc[i].x);
                acc[i].y = fmaf(a23.x, wr[2].y, acc[i].y);
                acc[i].z = fmaf(a23.x, wr[2].z, acc[i].z);
                acc[i].w = fmaf(a23.x, wr[2].w, acc[i].w);

                acc[i].x = fmaf(a23.y, wr[3].x, acc[i].x);
                acc[i].y = fmaf(a23.y, wr[3].y, acc[i].y);
                acc[i].z = fmaf(a23.y, wr[3].z, acc[i].z);
                acc[i].w = fmaf(a23.y, wr[3].w, acc[i].w);
            }
        }

        #pragma unroll
        for (int i = 0; i < 4; i++) {
            int row = row0 + r0 + i;
            if (row < N_NODES) {
                __half2 h01 = __floats2half2_rn(acc[i].x, acc[i].y);
                __half2 h23 = __floats2half2_rn(acc[i].z, acc[i].w);
                uint2 packed;
                packed.x = *reinterpret_cast<unsigned int*>(&h01);
                packed.y = *reinterpret_cast<unsigned int*>(&h23);
                g_Zh[row * 16 + tx] = packed;
            }
        }
    } else {
        // ---------------- bin path: 4 edges/thread ----------------
        int e0 = (part_id * 256 + threadIdx.x) * 4;
        if (e0 + 3 < N_EDGES) {
            int4   s = *reinterpret_cast<const int4*>(&src[e0]);
            int4   t = *reinterpret_cast<const int4*>(&dst[e0]);
            float4 v = *reinterpret_cast<const float4*>(&w[e0]);
            int p0 = atomicAdd(&g_cursor[t.x], 1);
            int p1 = atomicAdd(&g_cursor[t.y], 1);
            int p2 = atomicAdd(&g_cursor[t.z], 1);
            int p3 = atomicAdd(&g_cursor[t.w], 1);
            g_edges[p0] = make_int2(s.x, __float_as_int(v.x));
            g_edges[p1] = make_int2(s.y, __float_as_int(v.y));
            g_edges[p2] = make_int2(s.z, __float_as_int(v.z));
            g_edges[p3] = make_int2(s.w, __float_as_int(v.w));
        } else {
            for (int e = e0; e < N_EDGES; e++) {
                int t = __ldg(&dst[e]);
                int pos = atomicAdd(&g_cursor[t], 1);
                g_edges[pos] = make_int2(__ldg(&src[e]),
                                         __float_as_int(__ldg(&w[e])));
            }
        }
    }
}

// ---------------------------------------------------------------------------
// 4) gather-reduce over fp16 Z + bias + relu -> fp32 out.  One warp per
//    node. Edges processed in FIXED 16-edge batches with a fully-unrolled
//    8-iteration straight-line body: all 8 row loads per thread are
//    independent (MLP=8). Out-of-range edges clamp to a cached row with
//    zero weight.
// ---------------------------------------------------------------------------
__global__ __launch_bounds__(256) void gather_out_kernel(
        const float* __restrict__ b,
        float* __restrict__ out) {
    int gtid = blockIdx.x * blockDim.x + threadIdx.x;
    int node = gtid >> 5;
    int lane = gtid & 31;
    if (node >= N_NODES) return;
    int half = lane >> 4;
    int l    = lane & 15;

    int beg = __ldg(&g_rowptr[node]);
    int end = (node == N_NODES - 1) ? N_EDGES : __ldg(&g_rowptr[node + 1]);

    float4 acc = make_float4(0.f, 0.f, 0.f, 0.f);
    int last = end - 1;

    for (int base = beg; base < end; base += 16) {
        int n = end - base;
        if (n > 16) n = 16;
        int idx = base + (lane & 15);
        if (idx > last) idx = last;
        int2 e = g_edges[idx];                 // batch in lanes 0..15

        #pragma unroll
        for (int i = 0; i < 8; i++) {
            int k = 2 * i + half;              // half0: even, half1: odd
            int kk = (k < n) ? k : (n - 1);
            int   sx = __shfl_sync(0xFFFFFFFF, e.x, kk);
            float wv = __int_as_float(__shfl_sync(0xFFFFFFFF, e.y, kk));
            if (k >= n) wv = 0.f;

            uint2 zv = __ldg(&g_Zh[sx * 16 + l]);
            float2 f01 = __half22float2(*reinterpret_cast<__half2*>(&zv.x));
            float2 f23 = __half22float2(*reinterpret_cast<__half2*>(&zv.y));
            acc.x = fmaf(wv, f01.x, acc.x);
            acc.y = fmaf(wv, f01.y, acc.y);
            acc.z = fmaf(wv, f23.x, acc.z);
            acc.w = fmaf(wv, f23.y, acc.w);
        }
    }

    acc.x += __shfl_xor_sync(0xFFFFFFFF, acc.x, 16);
    acc.y += __shfl_xor_sync(0xFFFFFFFF, acc.y, 16);
    acc.z += __shfl_xor_sync(0xFFFFFFFF, acc.z, 16);
    acc.w += __shfl_xor_sync(0xFFFFFFFF, acc.w, 16);

    if (half == 0) {
        float4 bv = __ldg(&reinterpret_cast<const float4*>(b)[l]);
        float4 r;
        r.x = fmaxf(acc.x + bv.x, 0.f);
        r.y = fmaxf(acc.y + bv.y, 0.f);
        r.z = fmaxf(acc.z + bv.z, 0.f);
        r.w = fmaxf(acc.w + bv.w, 0.f);
        reinterpret_cast<float4*>(out)[node * 16 + l] = r;
    }
}

// ---------------------------------------------------------------------------
// Launch
// ---------------------------------------------------------------------------
extern "C" void kernel_launch(void* const* d_in, const int* in_sizes, int n_in,
                              void* d_out, int out_size) {
    const float* features = (const float*)d_in[0];   // [N_NODES, D]
    const int*   edge_src = (const int*)  d_in[1];   // [N_EDGES]
    const int*   edge_dst = (const int*)  d_in[2];   // [N_EDGES]
    const float* edge_w   = (const float*)d_in[3];   // [N_EDGES]
    const float* W        = (const float*)d_in[4];   // [D, D]
    const float* b        = (const float*)d_in[5];   // [1, D]
    float* out = (float*)d_out;                      // [N_NODES, D]

    void* count_ptr = nullptr;
    cudaGetSymbolAddress(&count_ptr, g_count);
    cudaMemsetAsync(count_ptr, 0, SCAN_PAD * sizeof(int));

    {
        int threads_total = (N_EDGES + 3) / 4;
        hist_kernel<<<(threads_total + 255) / 256, 256>>>(edge_dst);
    }
    scan_a_kernel<<<SCAN_NBLK, SCAN_BLK>>>();
    scan_c_kernel<<<(N_NODES + 255) / 256, 256>>>();

    bin_gemm_kernel<<<BIN_BLOCKS + GEMM_BLOCKS, 256>>>(
        edge_src, edge_dst, edge_w, features, W);

    {
        long long threads_total = (long long)N_NODES * 32;
        int blocks = (int)((threads_total + 255) / 256);
        gather_out_kernel<<<blocks, 256>>>(b, out);
    }
}

// round 11
// speedup vs baseline: 1.0147x; 1.0147x over previous
#include <cuda_runtime.h>
#include <cuda_fp16.h>

#define N_NODES 100000
#define N_EDGES 1600000
#define D 64

#define SCAN_BLK 1024
#define SCAN_NBLK 98                 // 98*1024 = 100352 >= 100000
#define SCAN_PAD (SCAN_NBLK * SCAN_BLK)

#define BIN_GRID   592               // persistent bin blocks (~4 per SM)
#define GEMM_GRID  1563              // 1563*64 = 100032 >= N_NODES

// Scratch (static __device__ arrays: allowed).
__device__ int   g_count[SCAN_PAD];
__device__ int   g_excl[SCAN_PAD];
__device__ int   g_bsum[SCAN_NBLK];
__device__ int   g_rowptr[N_NODES];
__device__ int   g_cursor[N_NODES];
__device__ int2  g_edges[N_EDGES];    // (src, w-as-int) binned by dst
__device__ uint2 g_Zh[N_NODES * 16];  // Z = X @ W in fp16: 64 halves/row = 128B

// ---------------------------------------------------------------------------
// 1) histogram of destination nodes — 4 edges/thread.
// ---------------------------------------------------------------------------
__global__ __launch_bounds__(256) void hist_kernel(const int* __restrict__ dst) {
    int e0 = (blockIdx.x * blockDim.x + threadIdx.x) * 4;
    if (e0 + 3 < N_EDGES) {
        int4 t = *reinterpret_cast<const int4*>(&dst[e0]);
        atomicAdd(&g_count[t.x], 1);
        atomicAdd(&g_count[t.y], 1);
        atomicAdd(&g_count[t.z], 1);
        atomicAdd(&g_count[t.w], 1);
    } else {
        for (int e = e0; e < N_EDGES; e++) atomicAdd(&g_count[__ldg(&dst[e])], 1);
    }
}

// ---------------------------------------------------------------------------
// 2a) per-block exclusive scan via warp shuffles (2 barriers).
// ---------------------------------------------------------------------------
__global__ __launch_bounds__(SCAN_BLK) void scan_a_kernel() {
    __shared__ int warp_sums[32];
    int t = threadIdx.x;
    int gid = blockIdx.x * SCAN_BLK + t;
    int lane = t & 31, wid = t >> 5;
    int c = g_count[gid];

    int v = c;                                 // inclusive scan within warp
    #pragma unroll
    for (int off = 1; off < 32; off <<= 1) {
        int n = __shfl_up_sync(0xFFFFFFFF, v, off);
        if (lane >= off) v += n;
    }
    if (lane == 31) warp_sums[wid] = v;
    __syncthreads();

    if (wid == 0) {
        int ws = warp_sums[lane];
        int s = ws;
        #pragma unroll
        for (int off = 1; off < 32; off <<= 1) {
            int n = __shfl_up_sync(0xFFFFFFFF, s, off);
            if (lane >= off) s += n;
        }
        warp_sums[lane] = s - ws;              // exclusive warp prefix
    }
    __syncthreads();

    g_excl[gid] = v - c + warp_sums[wid];      // block-exclusive
    if (t == SCAN_BLK - 1) g_bsum[blockIdx.x] = warp_sums[31] + v;
}

// 2b) finalize row_ptr (256 nodes per block lie inside one scan_a block).
__global__ __launch_bounds__(256) void scan_c_kernel() {
    __shared__ int s[SCAN_NBLK];
    __shared__ int prefix;
    int t = threadIdx.x;
    int sblk = blockIdx.x >> 2;
    if (t < SCAN_NBLK) s[t] = g_bsum[t];
    __syncthreads();
    if (t == 0) {
        int run = 0;
        for (int i = 0; i < sblk; i++) run += s[i];
        prefix = run;
    }
    __syncthreads();
    int i = blockIdx.x * 256 + t;
    if (i < N_NODES) {
        int v = g_excl[i] + prefix;
        g_rowptr[i] = v;
        g_cursor[i] = v;
    }
}

// ---------------------------------------------------------------------------
// 3) FUSED bin + gemm.  Blocks 0..BIN_GRID-1: persistent grid-stride bin
//    (resident all kernel, saturating the chip-wide atomic pipeline).
//    Remaining blocks: 64x64 fp32-smem GEMM tiles streaming through the
//    leftover occupancy. GEMM computes fp32, stores Z as fp16.
// ---------------------------------------------------------------------------
__global__ __launch_bounds__(256) void bin_gemm_kernel(
        const int*   __restrict__ src,
        const int*   __restrict__ dst,
        const float* __restrict__ w,
        const float* __restrict__ X,
        const float* __restrict__ W) {
    __shared__ float sm[2 * D * D];          // gemm path only (32 KB)

    if (blockIdx.x < BIN_GRID) {
        // ---------------- persistent bin path: grid-stride, 4 edges/iter ---
        const int stride = BIN_GRID * 256 * 4;          // 606208
        for (int e0 = (blockIdx.x * 256 + threadIdx.x) * 4;
             e0 < N_EDGES; e0 += stride) {
            if (e0 + 3 < N_EDGES) {
                int4   s = *reinterpret_cast<const int4*>(&src[e0]);
                int4   t = *reinterpret_cast<const int4*>(&dst[e0]);
                float4 v = *reinterpret_cast<const float4*>(&w[e0]);
                int p0 = atomicAdd(&g_cursor[t.x], 1);
                int p1 = atomicAdd(&g_cursor[t.y], 1);
                int p2 = atomicAdd(&g_cursor[t.z], 1);
                int p3 = atomicAdd(&g_cursor[t.w], 1);
                g_edges[p0] = make_int2(s.x, __float_as_int(v.x));
                g_edges[p1] = make_int2(s.y, __float_as_int(v.y));
                g_edges[p2] = make_int2(s.z, __float_as_int(v.z));
                g_edges[p3] = make_int2(s.w, __float_as_int(v.w));
            } else {
                for (int e = e0; e < N_EDGES; e++) {
                    int t = __ldg(&dst[e]);
                    int pos = atomicAdd(&g_cursor[t], 1);
                    g_edges[pos] = make_int2(__ldg(&src[e]),
                                             __float_as_int(__ldg(&w[e])));
                }
            }
        }
    } else {
        // ---------------- GEMM tile path ----------------
        int part_id = blockIdx.x - BIN_GRID;
        float* Ws = sm;                      // [k][c]
        float* As = sm + D * D;              // [r][k]
        int tid = threadIdx.x;
        int row0 = part_id * 64;

        const float4* W4 = reinterpret_cast<const float4*>(W);
        float4* Ws4 = reinterpret_cast<float4*>(Ws);
        #pragma unroll
        for (int i = tid; i < 1024; i += 256) Ws4[i] = W4[i];

        const float4* A4 = reinterpret_cast<const float4*>(X) + row0 * 16;
        float4* As4 = reinterpret_cast<float4*>(As);
        #pragma unroll
        for (int i = tid; i < 1024; i += 256) {
            int r = i >> 4;
            As4[i] = (row0 + r < N_NODES) ? A4[i]
                                          : make_float4(0.f, 0.f, 0.f, 0.f);
        }
        __syncthreads();

        int tx = tid & 15;
        int ty = tid >> 4;
        int c0 = tx * 4;
        int r0 = ty * 4;

        float4 acc[4];
        #pragma unroll
        for (int i = 0; i < 4; i++) acc[i] = make_float4(0.f, 0.f, 0.f, 0.f);

        #pragma unroll
        for (int k0 = 0; k0 < D; k0 += 4) {
            float4 wr0 = *reinterpret_cast<const float4*>(&Ws[(k0 + 0) * D + c0]);
            float4 wr1 = *reinterpret_cast<const float4*>(&Ws[(k0 + 1) * D + c0]);
            float4 wr2 = *reinterpret_cast<const float4*>(&Ws[(k0 + 2) * D + c0]);
            float4 wr3 = *reinterpret_cast<const float4*>(&Ws[(k0 + 3) * D + c0]);
            #pragma unroll
            for (int i = 0; i < 4; i++) {
                float4 av = *reinterpret_cast<const float4*>(&As[(r0 + i) * D + k0]);
                acc[i].x = fmaf(av.x, wr0.x, acc[i].x);
                acc[i].y = fmaf(av.x, wr0.y, acc[i].y);
                acc[i].z = fmaf(av.x, wr0.z, acc[i].z);
                acc[i].w = fmaf(av.x, wr0.w, acc[i].w);

                acc[i].x = fmaf(av.y, wr1.x, acc[i].x);
                acc[i].y = fmaf(av.y, wr1.y, acc[i].y);
                acc[i].z = fmaf(av.y, wr1.z, acc[i].z);
                acc[i].w = fmaf(av.y, wr1.w, acc[i].w);

                acc[i].x = fmaf(av.z, wr2.x, acc[i].x);
                acc[i].y = fmaf(av.z, wr2.y, acc[i].y);
                acc[i].z = fmaf(av.z, wr2.z, acc[i].z);
                acc[i].w = fmaf(av.z, wr2.w, acc[i].w);

                acc[i].x = fmaf(av.w, wr3.x, acc[i].x);
                acc[i].y = fmaf(av.w, wr3.y, acc[i].y);
                acc[i].z = fmaf(av.w, wr3.z, acc[i].z);
                acc[i].w = fmaf(av.w, wr3.w, acc[i].w);
            }
        }

        #pragma unroll
        for (int i = 0; i < 4; i++) {
            int row = row0 + r0 + i;
            if (row < N_NODES) {
                __half2 h01 = __floats2half2_rn(acc[i].x, acc[i].y);
                __half2 h23 = __floats2half2_rn(acc[i].z, acc[i].w);
                uint2 packed;
                packed.x = *reinterpret_cast<unsigned int*>(&h01);
                packed.y = *reinterpret_cast<unsigned int*>(&h23);
                g_Zh[row * 16 + tx] = packed;
            }
        }
    }
}

// ---------------------------------------------------------------------------
// 4) gather-reduce over fp16 Z + bias + relu -> fp32 out.  One warp per
//    node; 32-edge coalesced batches + shfl broadcast; half-warps process
//    even/odd edges, each lane loads 8B (4 halves). fp32 accumulation.
// ---------------------------------------------------------------------------
__global__ __launch_bounds__(256) void gather_out_kernel(
        const float* __restrict__ b,
        float* __restrict__ out) {
    int gtid = blockIdx.x * blockDim.x + threadIdx.x;
    int node = gtid >> 5;
    int lane = gtid & 31;
    if (node >= N_NODES) return;
    int half = lane >> 4;
    int l    = lane & 15;

    int beg = __ldg(&g_rowptr[node]);
    int end = (node == N_NODES - 1) ? N_EDGES : __ldg(&g_rowptr[node + 1]);

    float4 acc = make_float4(0.f, 0.f, 0.f, 0.f);

    for (int base = beg; base < end; base += 32) {
        int idx = base + lane;
        int2 e = (idx < end) ? g_edges[idx] : make_int2(0, 0);
        int n = end - base;
        if (n > 32) n = 32;

        #pragma unroll 4
        for (int k2 = 0; k2 < n; k2 += 2) {
            int k = k2 + half;                 // half0: even, half1: odd
            int kk = (k < n) ? k : (n - 1);    // keep shfl convergent
            int   sx = __shfl_sync(0xFFFFFFFF, e.x, kk);
            float wv = __int_as_float(__shfl_sync(0xFFFFFFFF, e.y, kk));
            if (k >= n) wv = 0.f;

            uint2 zv = __ldg(&g_Zh[sx * 16 + l]);
            float2 f01 = __half22float2(*reinterpret_cast<__half2*>(&zv.x));
            float2 f23 = __half22float2(*reinterpret_cast<__half2*>(&zv.y));
            acc.x = fmaf(wv, f01.x, acc.x);
            acc.y = fmaf(wv, f01.y, acc.y);
            acc.z = fmaf(wv, f23.x, acc.z);
            acc.w = fmaf(wv, f23.y, acc.w);
        }
    }

    acc.x += __shfl_xor_sync(0xFFFFFFFF, acc.x, 16);
    acc.y += __shfl_xor_sync(0xFFFFFFFF, acc.y, 16);
    acc.z += __shfl_xor_sync(0xFFFFFFFF, acc.z, 16);
    acc.w += __shfl_xor_sync(0xFFFFFFFF, acc.w, 16);

    if (half == 0) {
        float4 bv = __ldg(&reinterpret_cast<const float4*>(b)[l]);
        float4 r;
        r.x = fmaxf(acc.x + bv.x, 0.f);
        r.y = fmaxf(acc.y + bv.y, 0.f);
        r.z = fmaxf(acc.z + bv.z, 0.f);
        r.w = fmaxf(acc.w + bv.w, 0.f);
        reinterpret_cast<float4*>(out)[node * 16 + l] = r;
    }
}

// ---------------------------------------------------------------------------
// Launch
// ---------------------------------------------------------------------------
extern "C" void kernel_launch(void* const* d_in, const int* in_sizes, int n_in,
                              void* d_out, int out_size) {
    const float* features = (const float*)d_in[0];   // [N_NODES, D]
    const int*   edge_src = (const int*)  d_in[1];   // [N_EDGES]
    const int*   edge_dst = (const int*)  d_in[2];   // [N_EDGES]
    const float* edge_w   = (const float*)d_in[3];   // [N_EDGES]
    const float* W        = (const float*)d_in[4];   // [D, D]
    const float* b        = (const float*)d_in[5];   // [1, D]
    float* out = (float*)d_out;                      // [N_NODES, D]

    void* count_ptr = nullptr;
    cudaGetSymbolAddress(&count_ptr, g_count);
    cudaMemsetAsync(count_ptr, 0, SCAN_PAD * sizeof(int));

    {
        int threads_total = (N_EDGES + 3) / 4;
        hist_kernel<<<(threads_total + 255) / 256, 256>>>(edge_dst);
    }
    scan_a_kernel<<<SCAN_NBLK, SCAN_BLK>>>();
    scan_c_kernel<<<(N_NODES + 255) / 256, 256>>>();

    bin_gemm_kernel<<<BIN_GRID + GEMM_GRID, 256>>>(
        edge_src, edge_dst, edge_w, features, W);

    {
        long long threads_total = (long long)N_NODES * 32;
        int blocks = (int)((threads_total + 255) / 256);
        gather_out_kernel<<<blocks, 256>>>(b, out);
    }
}

// round 13
// speedup vs baseline: 1.0535x; 1.0383x over previous
#include <cuda_runtime.h>
#include <cuda_fp16.h>

#define N_NODES 100000
#define N_EDGES 1600000
#define D 64

#define SCAN_BLK 1024
#define SCAN_NBLK 98                 // 98*1024 = 100352 >= 100000
#define SCAN_PAD (SCAN_NBLK * SCAN_BLK)

#define BIN_BLOCKS  1563             // 1563*256*4 = 1600512 >= N_EDGES
#define GEMM_BLOCKS 1563             // 1563*64 = 100032 >= N_NODES

// Scratch (static __device__ arrays: allowed).
__device__ int   g_count[SCAN_PAD];
__device__ int   g_excl[SCAN_PAD];
__device__ int   g_bsum[SCAN_NBLK];
__device__ int   g_rowptr[N_NODES];
__device__ int   g_rank[N_EDGES];     // per-edge rank within its dst bin
__device__ int2  g_edges[N_EDGES];    // (src, w-as-int) binned by dst
__device__ uint2 g_Zh[N_NODES * 16];  // Z = X @ W in fp16: 64 halves/row = 128B

// ---------------------------------------------------------------------------
// 1) histogram of destination nodes + rank recording — 4 edges/thread.
//    The atomic's return value IS the edge's slot within its bin; stored
//    coalesced (e-indexed), so the store is fire-and-forget.
// ---------------------------------------------------------------------------
__global__ __launch_bounds__(256) void hist_kernel(const int* __restrict__ dst) {
    int e0 = (blockIdx.x * blockDim.x + threadIdx.x) * 4;
    if (e0 + 3 < N_EDGES) {
        int4 t = *reinterpret_cast<const int4*>(&dst[e0]);
        int4 r;
        r.x = atomicAdd(&g_count[t.x], 1);
        r.y = atomicAdd(&g_count[t.y], 1);
        r.z = atomicAdd(&g_count[t.z], 1);
        r.w = atomicAdd(&g_count[t.w], 1);
        *reinterpret_cast<int4*>(&g_rank[e0]) = r;
    } else {
        for (int e = e0; e < N_EDGES; e++)
            g_rank[e] = atomicAdd(&g_count[__ldg(&dst[e])], 1);
    }
}

// ---------------------------------------------------------------------------
// 2a) per-block exclusive scan via warp shuffles (2 barriers).
// ---------------------------------------------------------------------------
__global__ __launch_bounds__(SCAN_BLK) void scan_a_kernel() {
    __shared__ int warp_sums[32];
    int t = threadIdx.x;
    int gid = blockIdx.x * SCAN_BLK + t;
    int lane = t & 31, wid = t >> 5;
    int c = g_count[gid];

    int v = c;                                 // inclusive scan within warp
    #pragma unroll
    for (int off = 1; off < 32; off <<= 1) {
        int n = __shfl_up_sync(0xFFFFFFFF, v, off);
        if (lane >= off) v += n;
    }
    if (lane == 31) warp_sums[wid] = v;
    __syncthreads();

    if (wid == 0) {
        int ws = warp_sums[lane];
        int s = ws;
        #pragma unroll
        for (int off = 1; off < 32; off <<= 1) {
            int n = __shfl_up_sync(0xFFFFFFFF, s, off);
            if (lane >= off) s += n;
        }
        warp_sums[lane] = s - ws;              // exclusive warp prefix
    }
    __syncthreads();

    g_excl[gid] = v - c + warp_sums[wid];      // block-exclusive
    if (t == SCAN_BLK - 1) g_bsum[blockIdx.x] = warp_sums[31] + v;
}

// 2b) finalize row_ptr (256 nodes per block lie inside one scan_a block).
__global__ __launch_bounds__(256) void scan_c_kernel() {
    __shared__ int s[SCAN_NBLK];
    __shared__ int prefix;
    int t = threadIdx.x;
    int sblk = blockIdx.x >> 2;
    if (t < SCAN_NBLK) s[t] = g_bsum[t];
    __syncthreads();
    if (t == 0) {
        int run = 0;
        for (int i = 0; i < sblk; i++) run += s[i];
        prefix = run;
    }
    __syncthreads();
    int i = blockIdx.x * 256 + t;
    if (i < N_NODES) g_rowptr[i] = g_excl[i] + prefix;
}

// ---------------------------------------------------------------------------
// 3) FUSED bin + gemm (1:1 interleave, R9 config).  Bin path is now
//    ATOMIC-FREE: pos = rowptr[dst] + rank, all loads coalesced except the
//    L2-resident rowptr gather; the scattered int2 store has no consumer.
// ---------------------------------------------------------------------------
__global__ __launch_bounds__(256) void bin_gemm_kernel(
        const int*   __restrict__ src,
        const int*   __restrict__ dst,
        const float* __restrict__ w,
        const float* __restrict__ X,
        const float* __restrict__ W) {
    __shared__ float sm[2 * D * D];          // gemm path only (32 KB)

    int part_id = blockIdx.x >> 1;

    if (blockIdx.x & 1) {
        // ---------------- GEMM tile path ----------------
        float* Ws = sm;                      // [k][c]
        float* As = sm + D * D;              // [r][k]
        int tid = threadIdx.x;
        int row0 = part_id * 64;

        const float4* W4 = reinterpret_cast<const float4*>(W);
        float4* Ws4 = reinterpret_cast<float4*>(Ws);
        #pragma unroll
        for (int i = tid; i < 1024; i += 256) Ws4[i] = W4[i];

        const float4* A4 = reinterpret_cast<const float4*>(X) + row0 * 16;
        float4* As4 = reinterpret_cast<float4*>(As);
        #pragma unroll
        for (int i = tid; i < 1024; i += 256) {
            int r = i >> 4;
            As4[i] = (row0 + r < N_NODES) ? A4[i]
                                          : make_float4(0.f, 0.f, 0.f, 0.f);
        }
        __syncthreads();

        int tx = tid & 15;
        int ty = tid >> 4;
        int c0 = tx * 4;
        int r0 = ty * 4;

        float4 acc[4];
        #pragma unroll
        for (int i = 0; i < 4; i++) acc[i] = make_float4(0.f, 0.f, 0.f, 0.f);

        #pragma unroll
        for (int k0 = 0; k0 < D; k0 += 4) {
            float4 wr0 = *reinterpret_cast<const float4*>(&Ws[(k0 + 0) * D + c0]);
            float4 wr1 = *reinterpret_cast<const float4*>(&Ws[(k0 + 1) * D + c0]);
            float4 wr2 = *reinterpret_cast<const float4*>(&Ws[(k0 + 2) * D + c0]);
            float4 wr3 = *reinterpret_cast<const float4*>(&Ws[(k0 + 3) * D + c0]);
            #pragma unroll
            for (int i = 0; i < 4; i++) {
                float4 av = *reinterpret_cast<const float4*>(&As[(r0 + i) * D + k0]);
                acc[i].x = fmaf(av.x, wr0.x, acc[i].x);
                acc[i].y = fmaf(av.x, wr0.y, acc[i].y);
                acc[i].z = fmaf(av.x, wr0.z, acc[i].z);
                acc[i].w = fmaf(av.x, wr0.w, acc[i].w);

                acc[i].x = fmaf(av.y, wr1.x, acc[i].x);
                acc[i].y = fmaf(av.y, wr1.y, acc[i].y);
                acc[i].z = fmaf(av.y, wr1.z, acc[i].z);
                acc[i].w = fmaf(av.y, wr1.w, acc[i].w);

                acc[i].x = fmaf(av.z, wr2.x, acc[i].x);
                acc[i].y = fmaf(av.z, wr2.y, acc[i].y);
                acc[i].z = fmaf(av.z, wr2.z, acc[i].z);
                acc[i].w = fmaf(av.z, wr2.w, acc[i].w);

                acc[i].x = fmaf(av.w, wr3.x, acc[i].x);
                acc[i].y = fmaf(av.w, wr3.y, acc[i].y);
                acc[i].z = fmaf(av.w, wr3.z, acc[i].z);
                acc[i].w = fmaf(av.w, wr3.w, acc[i].w);
            }
        }

        #pragma unroll
        for (int i = 0; i < 4; i++) {
            int row = row0 + r0 + i;
            if (row < N_NODES) {
                __half2 h01 = __floats2half2_rn(acc[i].x, acc[i].y);
                __half2 h23 = __floats2half2_rn(acc[i].z, acc[i].w);
                uint2 packed;
                packed.x = *reinterpret_cast<unsigned int*>(&h01);
                packed.y = *reinterpret_cast<unsigned int*>(&h23);
                g_Zh[row * 16 + tx] = packed;
            }
        }
    } else {
        // ---------------- bin path: atomic-free, 4 edges/thread ----------
        int e0 = (part_id * 256 + threadIdx.x) * 4;
        if (e0 + 3 < N_EDGES) {
            int4   s = *reinterpret_cast<const int4*>(&src[e0]);
            int4   t = *reinterpret_cast<const int4*>(&dst[e0]);
            int4   r = *reinterpret_cast<const int4*>(&g_rank[e0]);
            float4 v = *reinterpret_cast<const float4*>(&w[e0]);
            int p0 = __ldg(&g_rowptr[t.x]) + r.x;
            int p1 = __ldg(&g_rowptr[t.y]) + r.y;
            int p2 = __ldg(&g_rowptr[t.z]) + r.z;
            int p3 = __ldg(&g_rowptr[t.w]) + r.w;
            g_edges[p0] = make_int2(s.x, __float_as_int(v.x));
            g_edges[p1] = make_int2(s.y, __float_as_int(v.y));
            g_edges[p2] = make_int2(s.z, __float_as_int(v.z));
            g_edges[p3] = make_int2(s.w, __float_as_int(v.w));
        } else {
            for (int e = e0; e < N_EDGES; e++) {
                int t = __ldg(&dst[e]);
                int pos = __ldg(&g_rowptr[t]) + g_rank[e];
                g_edges[pos] = make_int2(__ldg(&src[e]),
                                         __float_as_int(__ldg(&w[e])));
            }
        }
    }
}

// ---------------------------------------------------------------------------
// 4) gather-reduce over fp16 Z + bias + relu -> fp32 out.  One warp per
//    node; 32-edge coalesced batches + shfl broadcast; half-warps process
//    even/odd edges, each lane loads 8B (4 halves). fp32 accumulation.
// ---------------------------------------------------------------------------
__global__ __launch_bounds__(256) void gather_out_kernel(
        const float* __restrict__ b,
        float* __restrict__ out) {
    int gtid = blockIdx.x * blockDim.x + threadIdx.x;
    int node = gtid >> 5;
    int lane = gtid & 31;
    if (node >= N_NODES) return;
    int half = lane >> 4;
    int l    = lane & 15;

    int beg = __ldg(&g_rowptr[node]);
    int end = (node == N_NODES - 1) ? N_EDGES : __ldg(&g_rowptr[node + 1]);

    float4 acc = make_float4(0.f, 0.f, 0.f, 0.f);

    for (int base = beg; base < end; base += 32) {
        int idx = base + lane;
        int2 e = (idx < end) ? g_edges[idx] : make_int2(0, 0);
        int n = end - base;
        if (n > 32) n = 32;

        #pragma unroll 4
        for (int k2 = 0; k2 < n; k2 += 2) {
            int k = k2 + half;                 // half0: even, half1: odd
            int kk = (k < n) ? k : (n - 1);    // keep shfl convergent
            int   sx = __shfl_sync(0xFFFFFFFF, e.x, kk);
            float wv = __int_as_float(__shfl_sync(0xFFFFFFFF, e.y, kk));
            if (k >= n) wv = 0.f;

            uint2 zv = __ldg(&g_Zh[sx * 16 + l]);
            float2 f01 = __half22float2(*reinterpret_cast<__half2*>(&zv.x));
            float2 f23 = __half22float2(*reinterpret_cast<__half2*>(&zv.y));
            acc.x = fmaf(wv, f01.x, acc.x);
            acc.y = fmaf(wv, f01.y, acc.y);
            acc.z = fmaf(wv, f23.x, acc.z);
            acc.w = fmaf(wv, f23.y, acc.w);
        }
    }

    acc.x += __shfl_xor_sync(0xFFFFFFFF, acc.x, 16);
    acc.y += __shfl_xor_sync(0xFFFFFFFF, acc.y, 16);
    acc.z += __shfl_xor_sync(0xFFFFFFFF, acc.z, 16);
    acc.w += __shfl_xor_sync(0xFFFFFFFF, acc.w, 16);

    if (half == 0) {
        float4 bv = __ldg(&reinterpret_cast<const float4*>(b)[l]);
        float4 r;
        r.x = fmaxf(acc.x + bv.x, 0.f);
        r.y = fmaxf(acc.y + bv.y, 0.f);
        r.z = fmaxf(acc.z + bv.z, 0.f);
        r.w = fmaxf(acc.w + bv.w, 0.f);
        reinterpret_cast<float4*>(out)[node * 16 + l] = r;
    }
}

// ---------------------------------------------------------------------------
// Launch
// ---------------------------------------------------------------------------
extern "C" void kernel_launch(void* const* d_in, const int* in_sizes, int n_in,
                              void* d_out, int out_size) {
    const float* features = (const float*)d_in[0];   // [N_NODES, D]
    const int*   edge_src = (const int*)  d_in[1];   // [N_EDGES]
    const int*   edge_dst = (const int*)  d_in[2];   // [N_EDGES]
    const float* edge_w   = (const float*)d_in[3];   // [N_EDGES]
    const float* W        = (const float*)d_in[4];   // [D, D]
    const float* b        = (const float*)d_in[5];   // [1, D]
    float* out = (float*)d_out;                      // [N_NODES, D]

    void* count_ptr = nullptr;
    cudaGetSymbolAddress(&count_ptr, g_count);
    cudaMemsetAsync(count_ptr, 0, SCAN_PAD * sizeof(int));

    {
        int threads_total = (N_EDGES + 3) / 4;
        hist_kernel<<<(threads_total + 255) / 256, 256>>>(edge_dst);
    }
    scan_a_kernel<<<SCAN_NBLK, SCAN_BLK>>>();
    scan_c_kernel<<<(N_NODES + 255) / 256, 256>>>();

    bin_gemm_kernel<<<BIN_BLOCKS + GEMM_BLOCKS, 256>>>(
        edge_src, edge_dst, edge_w, features, W);

    {
        long long threads_total = (long long)N_NODES * 32;
        int blocks = (int)((threads_total + 255) / 256);
        gather_out_kernel<<<blocks, 256>>>(b, out);
    }
}

// round 14
// speedup vs baseline: 1.1278x; 1.0705x over previous
#include <cuda_runtime.h>
#include <cuda_fp16.h>

#define N_NODES 100000
#define N_EDGES 1600000
#define D 64

#define SCAN_BLK 1024
#define SCAN_NBLK 98                 // 98*1024 = 100352 >= 100000
#define SCAN_PAD (SCAN_NBLK * SCAN_BLK)

#define BIN_BLOCKS  1563             // 1563*256*4 = 1600512 >= N_EDGES
#define GEMM_BLOCKS 1563             // 1563*64 = 100032 >= N_NODES

// Scratch (static __device__ arrays: allowed).
__device__ int   g_count[SCAN_PAD];
__device__ int   g_excl[SCAN_PAD];
__device__ int   g_bsum[SCAN_NBLK];
__device__ int   g_rowptr[N_NODES];
__device__ int   g_cursor[N_NODES];
__device__ int2  g_edges[N_EDGES];    // (src, w-as-int) binned by dst
__device__ uint2 g_Zh[N_NODES * 16];  // Z = X @ W in fp16: 64 halves/row = 128B

// ---------------------------------------------------------------------------
// 1) histogram of destination nodes — 4 edges/thread, no-return atomics.
// ---------------------------------------------------------------------------
__global__ __launch_bounds__(256) void hist_kernel(const int* __restrict__ dst) {
    int e0 = (blockIdx.x * blockDim.x + threadIdx.x) * 4;
    if (e0 + 3 < N_EDGES) {
        int4 t = *reinterpret_cast<const int4*>(&dst[e0]);
        atomicAdd(&g_count[t.x], 1);
        atomicAdd(&g_count[t.y], 1);
        atomicAdd(&g_count[t.z], 1);
        atomicAdd(&g_count[t.w], 1);
    } else {
        for (int e = e0; e < N_EDGES; e++) atomicAdd(&g_count[__ldg(&dst[e])], 1);
    }
}

// ---------------------------------------------------------------------------
// 2a) per-block exclusive scan via warp shuffles (2 barriers).
// ---------------------------------------------------------------------------
__global__ __launch_bounds__(SCAN_BLK) void scan_a_kernel() {
    __shared__ int warp_sums[32];
    int t = threadIdx.x;
    int gid = blockIdx.x * SCAN_BLK + t;
    int lane = t & 31, wid = t >> 5;
    int c = g_count[gid];

    int v = c;                                 // inclusive scan within warp
    #pragma unroll
    for (int off = 1; off < 32; off <<= 1) {
        int n = __shfl_up_sync(0xFFFFFFFF, v, off);
        if (lane >= off) v += n;
    }
    if (lane == 31) warp_sums[wid] = v;
    __syncthreads();

    if (wid == 0) {
        int ws = warp_sums[lane];
        int s = ws;
        #pragma unroll
        for (int off = 1; off < 32; off <<= 1) {
            int n = __shfl_up_sync(0xFFFFFFFF, s, off);
            if (lane >= off) s += n;
        }
        warp_sums[lane] = s - ws;              // exclusive warp prefix
    }
    __syncthreads();

    g_excl[gid] = v - c + warp_sums[wid];      // block-exclusive
    if (t == SCAN_BLK - 1) g_bsum[blockIdx.x] = warp_sums[31] + v;
}

// 2b) finalize row_ptr (256 nodes per block lie inside one scan_a block).
__global__ __launch_bounds__(256) void scan_c_kernel() {
    __shared__ int s[SCAN_NBLK];
    __shared__ int prefix;
    int t = threadIdx.x;
    int sblk = blockIdx.x >> 2;
    if (t < SCAN_NBLK) s[t] = g_bsum[t];
    __syncthreads();
    if (t == 0) {
        int run = 0;
        for (int i = 0; i < sblk; i++) run += s[i];
        prefix = run;
    }
    __syncthreads();
    int i = blockIdx.x * 256 + t;
    if (i < N_NODES) {
        int v = g_excl[i] + prefix;
        g_rowptr[i] = v;
        g_cursor[i] = v;
    }
}

// ---------------------------------------------------------------------------
// 3) FUSED bin + gemm (1:1 interleave).  GEMM: W tile fp32 smem, A tile
//    fp16 smem (LDS 96B per 64 FMAs, was 128B). fp32 FMA math, fp16 Z out.
// ---------------------------------------------------------------------------
__global__ __launch_bounds__(256) void bin_gemm_kernel(
        const int*   __restrict__ src,
        const int*   __restrict__ dst,
        const float* __restrict__ w,
        const float* __restrict__ X,
        const float* __restrict__ W) {
    __shared__ float  Ws[D * D];             // 16 KB
    __shared__ __half Ash[64 * D];           // 8 KB

    int part_id = blockIdx.x >> 1;

    if (blockIdx.x & 1) {
        // ---------------- GEMM tile path ----------------
        int tid = threadIdx.x;
        int row0 = part_id * 64;

        const float4* W4 = reinterpret_cast<const float4*>(W);
        float4* Ws4 = reinterpret_cast<float4*>(Ws);
        #pragma unroll
        for (int i = tid; i < 1024; i += 256) Ws4[i] = W4[i];

        const float4* A4 = reinterpret_cast<const float4*>(X) + row0 * 16;
        uint2* As2 = reinterpret_cast<uint2*>(Ash);
        #pragma unroll
        for (int i = tid; i < 1024; i += 256) {
            int r = i >> 4;
            float4 v = (row0 + r < N_NODES) ? A4[i]
                                            : make_float4(0.f, 0.f, 0.f, 0.f);
            __half2 h01 = __floats2half2_rn(v.x, v.y);
            __half2 h23 = __floats2half2_rn(v.z, v.w);
            uint2 p;
            p.x = *reinterpret_cast<unsigned int*>(&h01);
            p.y = *reinterpret_cast<unsigned int*>(&h23);
            As2[i] = p;
        }
        __syncthreads();

        int tx = tid & 15;
        int ty = tid >> 4;
        int c0 = tx * 4;
        int r0 = ty * 4;

        float4 acc[4];
        #pragma unroll
        for (int i = 0; i < 4; i++) acc[i] = make_float4(0.f, 0.f, 0.f, 0.f);

        #pragma unroll
        for (int k0 = 0; k0 < D; k0 += 4) {
            float4 wr0 = *reinterpret_cast<const float4*>(&Ws[(k0 + 0) * D + c0]);
            float4 wr1 = *reinterpret_cast<const float4*>(&Ws[(k0 + 1) * D + c0]);
            float4 wr2 = *reinterpret_cast<const float4*>(&Ws[(k0 + 2) * D + c0]);
            float4 wr3 = *reinterpret_cast<const float4*>(&Ws[(k0 + 3) * D + c0]);
            #pragma unroll
            for (int i = 0; i < 4; i++) {
                uint2 u = As2[(r0 + i) * 16 + (k0 >> 2)];  // broadcast across tx
                float2 a01 = __half22float2(*reinterpret_cast<__half2*>(&u.x));
                float2 a23 = __half22float2(*reinterpret_cast<__half2*>(&u.y));

                acc[i].x = fmaf(a01.x, wr0.x, acc[i].x);
                acc[i].y = fmaf(a01.x, wr0.y, acc[i].y);
                acc[i].z = fmaf(a01.x, wr0.z, acc[i].z);
                acc[i].w = fmaf(a01.x, wr0.w, acc[i].w);

                acc[i].x = fmaf(a01.y, wr1.x, acc[i].x);
                acc[i].y = fmaf(a01.y, wr1.y, acc[i].y);
                acc[i].z = fmaf(a01.y, wr1.z, acc[i].z);
                acc[i].w = fmaf(a01.y, wr1.w, acc[i].w);

                acc[i].x = fmaf(a23.x, wr2.x, acc[i].x);
                acc[i].y = fmaf(a23.x, wr2.y, acc[i].y);
                acc[i].z = fmaf(a23.x, wr2.z, acc[i].z);
                acc[i].w = fmaf(a23.x, wr2.w, acc[i].w);

                acc[i].x = fmaf(a23.y, wr3.x, acc[i].x);
                acc[i].y = fmaf(a23.y, wr3.y, acc[i].y);
                acc[i].z = fmaf(a23.y, wr3.z, acc[i].z);
                acc[i].w = fmaf(a23.y, wr3.w, acc[i].w);
            }
        }

        #pragma unroll
        for (int i = 0; i < 4; i++) {
            int row = row0 + r0 + i;
            if (row < N_NODES) {
                __half2 h01 = __floats2half2_rn(acc[i].x, acc[i].y);
                __half2 h23 = __floats2half2_rn(acc[i].z, acc[i].w);
                uint2 packed;
                packed.x = *reinterpret_cast<unsigned int*>(&h01);
                packed.y = *reinterpret_cast<unsigned int*>(&h23);
                g_Zh[row * 16 + tx] = packed;
            }
        }
    } else {
        // ---------------- bin path: 4 edges/thread, atomic cursors -------
        int e0 = (part_id * 256 + threadIdx.x) * 4;
        if (e0 + 3 < N_EDGES) {
            int4   s = *reinterpret_cast<const int4*>(&src[e0]);
            int4   t = *reinterpret_cast<const int4*>(&dst[e0]);
            float4 v = *reinterpret_cast<const float4*>(&w[e0]);
            int p0 = atomicAdd(&g_cursor[t.x], 1);
            int p1 = atomicAdd(&g_cursor[t.y], 1);
            int p2 = atomicAdd(&g_cursor[t.z], 1);
            int p3 = atomicAdd(&g_cursor[t.w], 1);
            g_edges[p0] = make_int2(s.x, __float_as_int(v.x));
            g_edges[p1] = make_int2(s.y, __float_as_int(v.y));
            g_edges[p2] = make_int2(s.z, __float_as_int(v.z));
            g_edges[p3] = make_int2(s.w, __float_as_int(v.w));
        } else {
            for (int e = e0; e < N_EDGES; e++) {
                int t = __ldg(&dst[e]);
                int pos = atomicAdd(&g_cursor[t], 1);
                g_edges[pos] = make_int2(__ldg(&src[e]),
                                         __float_as_int(__ldg(&w[e])));
            }
        }
    }
}

// ---------------------------------------------------------------------------
// 4) gather-reduce over fp16 Z + bias + relu -> fp32 out.  HALF-WARP per
//    node: 16 lanes cover the full 128B Z row (8B each). 16-edge coalesced
//    batches; shfl broadcast with width 16 and a half-local mask so the two
//    halves of a warp run independent nodes (divergence-safe). No final
//    cross-lane reduction needed.
// ---------------------------------------------------------------------------
__global__ __launch_bounds__(256) void gather_out_kernel(
        const float* __restrict__ b,
        float* __restrict__ out) {
    int gtid = blockIdx.x * blockDim.x + threadIdx.x;
    int node = gtid >> 4;
    int l    = gtid & 15;
    if (node >= N_NODES) return;
    unsigned hmask = 0xFFFFu << (threadIdx.x & 16);   // this half's lanes

    int beg = __ldg(&g_rowptr[node]);
    int end = (node == N_NODES - 1) ? N_EDGES : __ldg(&g_rowptr[node + 1]);

    float4 acc = make_float4(0.f, 0.f, 0.f, 0.f);

    for (int base = beg; base < end; base += 16) {
        int idx = base + l;
        int2 e = (idx < end) ? g_edges[idx] : make_int2(0, 0);
        int n = end - base;
        if (n > 16) n = 16;

        #pragma unroll 4
        for (int k = 0; k < n; k++) {
            int   sx = __shfl_sync(hmask, e.x, k, 16);
            float wv = __int_as_float(__shfl_sync(hmask, e.y, k, 16));
            uint2 zv = __ldg(&g_Zh[sx * 16 + l]);
            float2 f01 = __half22float2(*reinterpret_cast<__half2*>(&zv.x));
            float2 f23 = __half22float2(*reinterpret_cast<__half2*>(&zv.y));
            acc.x = fmaf(wv, f01.x, acc.x);
            acc.y = fmaf(wv, f01.y, acc.y);
            acc.z = fmaf(wv, f23.x, acc.z);
            acc.w = fmaf(wv, f23.y, acc.w);
        }
    }

    float4 bv = __ldg(&reinterpret_cast<const float4*>(b)[l]);
    float4 r;
    r.x = fmaxf(acc.x + bv.x, 0.f);
    r.y = fmaxf(acc.y + bv.y, 0.f);
    r.z = fmaxf(acc.z + bv.z, 0.f);
    r.w = fmaxf(acc.w + bv.w, 0.f);
    reinterpret_cast<float4*>(out)[node * 16 + l] = r;
}

// ---------------------------------------------------------------------------
// Launch
// ---------------------------------------------------------------------------
extern "C" void kernel_launch(void* const* d_in, const int* in_sizes, int n_in,
                              void* d_out, int out_size) {
    const float* features = (const float*)d_in[0];   // [N_NODES, D]
    const int*   edge_src = (const int*)  d_in[1];   // [N_EDGES]
    const int*   edge_dst = (const int*)  d_in[2];   // [N_EDGES]
    const float* edge_w   = (const float*)d_in[3];   // [N_EDGES]
    const float* W        = (const float*)d_in[4];   // [D, D]
    const float* b        = (const float*)d_in[5];   // [1, D]
    float* out = (float*)d_out;                      // [N_NODES, D]

    void* count_ptr = nullptr;
    cudaGetSymbolAddress(&count_ptr, g_count);
    cudaMemsetAsync(count_ptr, 0, SCAN_PAD * sizeof(int));

    {
        int threads_total = (N_EDGES + 3) / 4;
        hist_kernel<<<(threads_total + 255) / 256, 256>>>(edge_dst);
    }
    scan_a_kernel<<<SCAN_NBLK, SCAN_BLK>>>();
    scan_c_kernel<<<(N_NODES + 255) / 256, 256>>>();

    bin_gemm_kernel<<<BIN_BLOCKS + GEMM_BLOCKS, 256>>>(
        edge_src, edge_dst, edge_w, features, W);

    {
        long long threads_total = (long long)N_NODES * 16;
        int blocks = (int)((threads_total + 255) / 256);
        gather_out_kernel<<<blocks, 256>>>(b, out);
    }
}

// round 17
// speedup vs baseline: 1.1798x; 1.0461x over previous
#include <cuda_runtime.h>
#include <cuda_fp16.h>
#include <cstdint>
#include <cstddef>

#define N_NODES 100000
#define N_EDGES 1600000
#define D 64

#define SCAN_BLK 1024
#define SCAN_NBLK 98                 // 98*1024 = 100352 >= 100000
#define SCAN_PAD (SCAN_NBLK * SCAN_BLK)

#define BIN_BLOCKS  1563             // 1563*256*4 = 1600512 >= N_EDGES
#define GEMM_BLOCKS 1563             // 1563*64 = 100032 >= N_NODES

#define SM_STRIDE 72                 // halves per smem row (144B, ldmatrix-safe)

// Scratch (static __device__ arrays: allowed).
__device__ int   g_count[SCAN_PAD];
__device__ int   g_excl[SCAN_PAD];
__device__ int   g_bsum[SCAN_NBLK];
__device__ int   g_rowptr[N_NODES];
__device__ int   g_cursor[N_NODES];
__device__ int2  g_edges[N_EDGES];    // (src, w-as-int) binned by dst
__device__ uint2 g_Zh[N_NODES * 16];  // Z = X @ W in fp16: 64 halves/row = 128B

// ---------------------------------------------------------------------------
// 1) histogram of destination nodes — 4 edges/thread, no-return atomics.
// ---------------------------------------------------------------------------
__global__ __launch_bounds__(256) void hist_kernel(const int* __restrict__ dst) {
    int e0 = (blockIdx.x * blockDim.x + threadIdx.x) * 4;
    if (e0 + 3 < N_EDGES) {
        int4 t = *reinterpret_cast<const int4*>(&dst[e0]);
        atomicAdd(&g_count[t.x], 1);
        atomicAdd(&g_count[t.y], 1);
        atomicAdd(&g_count[t.z], 1);
        atomicAdd(&g_count[t.w], 1);
    } else {
        for (int e = e0; e < N_EDGES; e++) atomicAdd(&g_count[__ldg(&dst[e])], 1);
    }
}

// ---------------------------------------------------------------------------
// 2a) per-block exclusive scan via warp shuffles (2 barriers).
// ---------------------------------------------------------------------------
__global__ __launch_bounds__(SCAN_BLK) void scan_a_kernel() {
    __shared__ int warp_sums[32];
    int t = threadIdx.x;
    int gid = blockIdx.x * SCAN_BLK + t;
    int lane = t & 31;
    int wid = t >> 5;
    int c = g_count[gid];

    int v = c;
    #pragma unroll
    for (int off = 1; off < 32; off <<= 1) {
        int n = __shfl_up_sync(0xFFFFFFFF, v, off);
        if (lane >= off) v += n;
    }
    if (lane == 31) warp_sums[wid] = v;
    __syncthreads();

    if (wid == 0) {
        int ws = warp_sums[lane];
        int s = ws;
        #pragma unroll
        for (int off = 1; off < 32; off <<= 1) {
            int n = __shfl_up_sync(0xFFFFFFFF, s, off);
            if (lane >= off) s += n;
        }
        warp_sums[lane] = s - ws;
    }
    __syncthreads();

    g_excl[gid] = v - c + warp_sums[wid];
    if (t == SCAN_BLK - 1) g_bsum[blockIdx.x] = warp_sums[31] + v;
}

// 2b) finalize row_ptr (256 nodes per block lie inside one scan_a block).
__global__ __launch_bounds__(256) void scan_c_kernel() {
    __shared__ int s[SCAN_NBLK];
    __shared__ int prefix;
    int t = threadIdx.x;
    int sblk = blockIdx.x >> 2;
    if (t < SCAN_NBLK) s[t] = g_bsum[t];
    __syncthreads();
    if (t == 0) {
        int run = 0;
        for (int i = 0; i < sblk; i++) run += s[i];
        prefix = run;
    }
    __syncthreads();
    int i = blockIdx.x * 256 + t;
    if (i < N_NODES) {
        int v = g_excl[i] + prefix;
        g_rowptr[i] = v;
        g_cursor[i] = v;
    }
}

// ---------------------------------------------------------------------------
// ldmatrix / mma helpers
// ---------------------------------------------------------------------------
__device__ __forceinline__ void ldmatrix_x4(unsigned int& r0, unsigned int& r1,
                                            unsigned int& r2, unsigned int& r3,
                                            unsigned int addr) {
    asm volatile("ldmatrix.sync.aligned.m8n8.x4.shared.b16 {%0,%1,%2,%3}, [%4];"
                 : "=r"(r0), "=r"(r1), "=r"(r2), "=r"(r3) : "r"(addr));
}

__device__ __forceinline__ void ldmatrix_x4_trans(unsigned int& r0, unsigned int& r1,
                                                  unsigned int& r2, unsigned int& r3,
                                                  unsigned int addr) {
    asm volatile("ldmatrix.sync.aligned.m8n8.x4.trans.shared.b16 {%0,%1,%2,%3}, [%4];"
                 : "=r"(r0), "=r"(r1), "=r"(r2), "=r"(r3) : "r"(addr));
}

__device__ __forceinline__ void mma_16x8x16(float* c, unsigned int a0, unsigned int a1,
                                            unsigned int a2, unsigned int a3,
                                            unsigned int b0, unsigned int b1) {
    asm volatile(
        "mma.sync.aligned.m16n8k16.row.col.f32.f16.f16.f32 "
        "{%0,%1,%2,%3}, {%4,%5,%6,%7}, {%8,%9}, {%0,%1,%2,%3};"
        : "+f"(c[0]), "+f"(c[1]), "+f"(c[2]), "+f"(c[3])
        : "r"(a0), "r"(a1), "r"(a2), "r"(a3), "r"(b0), "r"(b1));
}

__device__ __forceinline__ uint2 pack_half4(float x, float y, float z, float w) {
    __half2 h01 = __floats2half2_rn(x, y);
    __half2 h23 = __floats2half2_rn(z, w);
    uint2 p;
    p.x = *reinterpret_cast<unsigned int*>(&h01);
    p.y = *reinterpret_cast<unsigned int*>(&h23);
    return p;
}

// ---------------------------------------------------------------------------
// GEMM tile (HMMA): one 64x64 tile of Z = X @ W, fp16 smem, fp32 accum,
// fp16 Z out.  8 warps: (wid&3) -> 16-row strip, (wid>>2) -> 32-col strip.
// ---------------------------------------------------------------------------
__device__ void gemm_tile_hmma(int row0, const float* __restrict__ X,
                               const float* __restrict__ W,
                               __half* Ash, __half* Wsh) {
    int tid = threadIdx.x;

    // Fill W smem: [k][n] fp16, row stride SM_STRIDE.
    const float4* W4 = reinterpret_cast<const float4*>(W);
    for (int i = tid; i < 1024; i += 256) {
        int k = i >> 4;
        int n4 = i & 15;
        float4 v = W4[i];
        *reinterpret_cast<uint2*>(&Wsh[k * SM_STRIDE + n4 * 4]) =
            pack_half4(v.x, v.y, v.z, v.w);
    }
    // Fill A smem: [row][k] fp16.
    const float4* A4 = reinterpret_cast<const float4*>(X) + row0 * 16;
    for (int i = tid; i < 1024; i += 256) {
        int rrow = i >> 4;
        int k4 = i & 15;
        float4 v;
        if (row0 + rrow < N_NODES) v = A4[i];
        else v = make_float4(0.f, 0.f, 0.f, 0.f);
        *reinterpret_cast<uint2*>(&Ash[rrow * SM_STRIDE + k4 * 4]) =
            pack_half4(v.x, v.y, v.z, v.w);
    }
    __syncthreads();

    int wid = tid >> 5;
    int lane = tid & 31;
    int mb = (wid & 3) * 16;
    int nb = (wid >> 2) * 32;

    unsigned int a_base = (unsigned int)__cvta_generic_to_shared(Ash);
    unsigned int w_base = (unsigned int)__cvta_generic_to_shared(Wsh);

    int grp = lane >> 3;
    int i8 = lane & 7;

    float c0[4] = {0.f, 0.f, 0.f, 0.f};
    float c1[4] = {0.f, 0.f, 0.f, 0.f};
    float c2[4] = {0.f, 0.f, 0.f, 0.f};
    float c3[4] = {0.f, 0.f, 0.f, 0.f};

    #pragma unroll
    for (int k0 = 0; k0 < 64; k0 += 16) {
        int ar = mb + i8 + (grp & 1) * 8;
        int ak = k0 + (grp >> 1) * 8;
        unsigned int a0, a1, a2, a3;
        ldmatrix_x4(a0, a1, a2, a3, a_base + (unsigned int)(ar * SM_STRIDE + ak) * 2u);

        int bk = k0 + i8 + (grp & 1) * 8;
        int bn = nb + (grp >> 1) * 8;
        unsigned int b0, b1, b2, b3;
        ldmatrix_x4_trans(b0, b1, b2, b3,
                          w_base + (unsigned int)(bk * SM_STRIDE + bn) * 2u);
        unsigned int b4, b5, b6, b7;
        ldmatrix_x4_trans(b4, b5, b6, b7,
                          w_base + (unsigned int)(bk * SM_STRIDE + bn + 16) * 2u);

        mma_16x8x16(c0, a0, a1, a2, a3, b0, b1);
        mma_16x8x16(c1, a0, a1, a2, a3, b2, b3);
        mma_16x8x16(c2, a0, a1, a2, a3, b4, b5);
        mma_16x8x16(c3, a0, a1, a2, a3, b6, b7);
    }

    // Epilogue: cN[0,1] -> (row, col..col+1); cN[2,3] -> (row+8, ...)
    int rr = mb + (lane >> 2);
    int cc = (lane & 3) * 2;
    __half2* Zh2 = reinterpret_cast<__half2*>(g_Zh);
    int row_a = row0 + rr;
    int row_b = row0 + rr + 8;

    if (row_a < N_NODES) {
        Zh2[row_a * 32 + ((nb + 0 + cc) >> 1)]  = __floats2half2_rn(c0[0], c0[1]);
        Zh2[row_a * 32 + ((nb + 8 + cc) >> 1)]  = __floats2half2_rn(c1[0], c1[1]);
        Zh2[row_a * 32 + ((nb + 16 + cc) >> 1)] = __floats2half2_rn(c2[0], c2[1]);
        Zh2[row_a * 32 + ((nb + 24 + cc) >> 1)] = __floats2half2_rn(c3[0], c3[1]);
    }
    if (row_b < N_NODES) {
        Zh2[row_b * 32 + ((nb + 0 + cc) >> 1)]  = __floats2half2_rn(c0[2], c0[3]);
        Zh2[row_b * 32 + ((nb + 8 + cc) >> 1)]  = __floats2half2_rn(c1[2], c1[3]);
        Zh2[row_b * 32 + ((nb + 16 + cc) >> 1)] = __floats2half2_rn(c2[2], c2[3]);
        Zh2[row_b * 32 + ((nb + 24 + cc) >> 1)] = __floats2half2_rn(c3[2], c3[3]);
    }
}

// ---------------------------------------------------------------------------
// Bin path: 4 edges/thread, atomic cursors.
// ---------------------------------------------------------------------------
__device__ void bin_edges(int part_id, const int* __restrict__ src,
                          const int* __restrict__ dst,
                          const float* __restrict__ w) {
    int e0 = (part_id * 256 + threadIdx.x) * 4;
    if (e0 + 3 < N_EDGES) {
        int4 s = *reinterpret_cast<const int4*>(&src[e0]);
        int4 t = *reinterpret_cast<const int4*>(&dst[e0]);
        float4 v = *reinterpret_cast<const float4*>(&w[e0]);
        int p0 = atomicAdd(&g_cursor[t.x], 1);
        int p1 = atomicAdd(&g_cursor[t.y], 1);
        int p2 = atomicAdd(&g_cursor[t.z], 1);
        int p3 = atomicAdd(&g_cursor[t.w], 1);
        g_edges[p0] = make_int2(s.x, __float_as_int(v.x));
        g_edges[p1] = make_int2(s.y, __float_as_int(v.y));
        g_edges[p2] = make_int2(s.z, __float_as_int(v.z));
        g_edges[p3] = make_int2(s.w, __float_as_int(v.w));
    } else {
        for (int e = e0; e < N_EDGES; e++) {
            int t = __ldg(&dst[e]);
            int pos = atomicAdd(&g_cursor[t], 1);
            g_edges[pos] = make_int2(__ldg(&src[e]),
                                     __float_as_int(__ldg(&w[e])));
        }
    }
}

// ---------------------------------------------------------------------------
// 3) FUSED bin + gemm (1:1 interleave).
// ---------------------------------------------------------------------------
__global__ __launch_bounds__(256) void bin_gemm_kernel(
        const int*   __restrict__ src,
        const int*   __restrict__ dst,
        const float* __restrict__ w,
        const float* __restrict__ X,
        const float* __restrict__ W) {
    __shared__ __half Ash[64 * SM_STRIDE];   // 9 KB
    __shared__ __half Wsh[64 * SM_STRIDE];   // 9 KB

    int part_id = blockIdx.x >> 1;
    if (blockIdx.x & 1) {
        gemm_tile_hmma(part_id * 64, X, W, Ash, Wsh);
    } else {
        bin_edges(part_id, src, dst, w);
    }
}

// ---------------------------------------------------------------------------
// 4) gather-reduce over fp16 Z + bias + relu -> fp32 out.  HALF-WARP per
//    node (16 lanes = full 128B row); 16-edge coalesced batches + width-16
//    shfl broadcast; fp32 accumulation; no cross-lane reduction.
// ---------------------------------------------------------------------------
__global__ __launch_bounds__(256) void gather_out_kernel(
        const float* __restrict__ b,
        float* __restrict__ out) {
    int gtid = blockIdx.x * blockDim.x + threadIdx.x;
    int node = gtid >> 4;
    int l = gtid & 15;
    if (node >= N_NODES) return;
    unsigned int hmask = 0xFFFFu << (threadIdx.x & 16);

    int beg = __ldg(&g_rowptr[node]);
    int end = (node == N_NODES - 1) ? N_EDGES : __ldg(&g_rowptr[node + 1]);

    float4 acc = make_float4(0.f, 0.f, 0.f, 0.f);

    for (int base = beg; base < end; base += 16) {
        int idx = base + l;
        int2 e = (idx < end) ? g_edges[idx] : make_int2(0, 0);
        int n = end - base;
        if (n > 16) n = 16;

        #pragma unroll 4
        for (int k = 0; k < n; k++) {
            int sx = __shfl_sync(hmask, e.x, k, 16);
            float wv = __int_as_float(__shfl_sync(hmask, e.y, k, 16));
            uint2 zv = __ldg(&g_Zh[sx * 16 + l]);
            float2 f01 = __half22float2(*reinterpret_cast<__half2*>(&zv.x));
            float2 f23 = __half22float2(*reinterpret_cast<__half2*>(&zv.y));
            acc.x = fmaf(wv, f01.x, acc.x);
            acc.y = fmaf(wv, f01.y, acc.y);
            acc.z = fmaf(wv, f23.x, acc.z);
            acc.w = fmaf(wv, f23.y, acc.w);
        }
    }

    float4 bv = __ldg(&reinterpret_cast<const float4*>(b)[l]);
    float4 res;
    res.x = fmaxf(acc.x + bv.x, 0.f);
    res.y = fmaxf(acc.y + bv.y, 0.f);
    res.z = fmaxf(acc.z + bv.z, 0.f);
    res.w = fmaxf(acc.w + bv.w, 0.f);
    reinterpret_cast<float4*>(out)[node * 16 + l] = res;
}

// ---------------------------------------------------------------------------
// Launch
// ---------------------------------------------------------------------------
extern "C" void kernel_launch(void* const* d_in, const int* in_sizes, int n_in,
                              void* d_out, int out_size) {
    const float* features = (const float*)d_in[0];   // [N_NODES, D]
    const int*   edge_src = (const int*)  d_in[1];   // [N_EDGES]
    const int*   edge_dst = (const int*)  d_in[2];   // [N_EDGES]
    const float* edge_w   = (const float*)d_in[3];   // [N_EDGES]
    const float* W        = (const float*)d_in[4];   // [D, D]
    const float* b        = (const float*)d_in[5];   // [1, D]
    float* out = (float*)d_out;                      // [N_NODES, D]

    void* count_ptr = nullptr;
    cudaGetSymbolAddress(&count_ptr, g_count);
    cudaMemsetAsync(count_ptr, 0, SCAN_PAD * sizeof(int));

    {
        int threads_total = (N_EDGES + 3) / 4;
        hist_kernel<<<(threads_total + 255) / 256, 256>>>(edge_dst);
    }
    scan_a_kernel<<<SCAN_NBLK, SCAN_BLK>>>();
    scan_c_kernel<<<(N_NODES + 255) / 256, 256>>>();

    bin_gemm_kernel<<<BIN_BLOCKS + GEMM_BLOCKS, 256>>>(
        edge_src, edge_dst, edge_w, features, W);

    {
        long long threads_total = (long long)N_NODES * 16;
        int blocks = (int)((threads_total + 255) / 256);
        gather_out_kernel<<<blocks, 256>>>(b, out);
    }
}